// round 1
// baseline (speedup 1.0000x reference)
#include <cuda_runtime.h>
#include <cuda_bf16.h>

// GCN layer: out = Dr^{-1/2} * A * Ds^{-1/2} * (X W + b)
// Strategy: degrees -> CSR(receiver) build -> fused GEMM(prescale) -> warp-per-node gather (postscale)

#define MAX_N 100000
#define MAX_E 1600000
#define D 128          // D_IN == D_OUT == 128
#define DV 32          // D/4 (float4 lanes)

// ---- device scratch (no allocation allowed) ----
__device__ float4 g_h[(size_t)MAX_N * DV];     // scaled hidden features, 51.2 MB
__device__ int    g_deg_s[MAX_N];
__device__ int    g_deg_r[MAX_N];
__device__ int    g_row_start[MAX_N + 1];
__device__ int    g_row_cur[MAX_N];
__device__ int    g_edge_src[MAX_E];

// ---------------------------------------------------------------------------
__global__ void zero_kernel(int N) {
    int i = blockIdx.x * blockDim.x + threadIdx.x;
    if (i < N) { g_deg_s[i] = 0; g_deg_r[i] = 0; }
}

// ---------------------------------------------------------------------------
__global__ void degree_kernel(const int* __restrict__ senders,
                              const int* __restrict__ receivers, int E) {
    int e = blockIdx.x * blockDim.x + threadIdx.x;
    if (e < E) {
        atomicAdd(&g_deg_s[senders[e]], 1);
        atomicAdd(&g_deg_r[receivers[e]], 1);
    }
}

// ---------------------------------------------------------------------------
// Single-block exclusive scan of g_deg_r -> g_row_start / g_row_cur.
__global__ void scan_kernel(int N, int E) {
    __shared__ int sums[1024];
    int t = threadIdx.x;
    int chunk = (N + 1023) / 1024;
    int beg = t * chunk;
    int end = min(beg + chunk, N);

    int s = 0;
    for (int i = beg; i < end; i++) s += g_deg_r[i];
    sums[t] = s;
    __syncthreads();

    // inclusive Hillis-Steele scan over per-thread totals
    for (int off = 1; off < 1024; off <<= 1) {
        int tmp = (t >= off) ? sums[t - off] : 0;
        __syncthreads();
        if (t >= off) sums[t] += tmp;
        __syncthreads();
    }

    int run = (t == 0) ? 0 : sums[t - 1];   // exclusive base for this chunk
    for (int i = beg; i < end; i++) {
        g_row_start[i] = run;
        g_row_cur[i]   = run;
        run += g_deg_r[i];
    }
    if (t == 1023) g_row_start[N] = sums[1023];  // == E
}

// ---------------------------------------------------------------------------
__global__ void fill_kernel(const int* __restrict__ senders,
                            const int* __restrict__ receivers, int E) {
    int e = blockIdx.x * blockDim.x + threadIdx.x;
    if (e < E) {
        int pos = atomicAdd(&g_row_cur[receivers[e]], 1);
        g_edge_src[pos] = senders[e];
    }
}

// ---------------------------------------------------------------------------
// GEMM: h[r,:] = (x[r,:] @ W + b) * rsqrt(max(deg_s[r],1))
// 64-row tiles, full 128x128 W resident in smem, 256 threads,
// each thread owns 8 rows x 4 cols (float4 accumulators).
__global__ __launch_bounds__(256, 2)
void gemm_kernel(const float* __restrict__ x, const float* __restrict__ W,
                 const float* __restrict__ bias, int N) {
    extern __shared__ float sm[];
    float4* Wsv = (float4*)sm;                 // 128*32 float4 = 64 KB
    float*  Xs  = sm + D * D;                  // 64*128 floats = 32 KB
    float4* Xsv = (float4*)Xs;

    int t = threadIdx.x;
    int rowTile = blockIdx.x * 64;

    const float4* Wv = (const float4*)W;
    for (int i = t; i < D * DV; i += 256) Wsv[i] = Wv[i];

    const float4* Xv = (const float4*)x;
    for (int i = t; i < 64 * DV; i += 256) {
        int r = rowTile + (i >> 5);            // i / 32
        Xsv[i] = (r < N) ? Xv[(size_t)r * DV + (i & 31)]
                         : make_float4(0.f, 0.f, 0.f, 0.f);
    }
    __syncthreads();

    int warp = t >> 5, lane = t & 31;
    int r0 = warp * 8;

    float4 acc[8];
#pragma unroll
    for (int i = 0; i < 8; i++) acc[i] = make_float4(0.f, 0.f, 0.f, 0.f);

#pragma unroll 4
    for (int k = 0; k < D; k++) {
        float4 w = Wsv[k * DV + lane];
#pragma unroll
        for (int i = 0; i < 8; i++) {
            float xv = Xs[(r0 + i) * D + k];
            acc[i].x = fmaf(xv, w.x, acc[i].x);
            acc[i].y = fmaf(xv, w.y, acc[i].y);
            acc[i].z = fmaf(xv, w.z, acc[i].z);
            acc[i].w = fmaf(xv, w.w, acc[i].w);
        }
    }

    float4 b = ((const float4*)bias)[lane];
#pragma unroll
    for (int i = 0; i < 8; i++) {
        int r = rowTile + r0 + i;
        if (r < N) {
            float sc = rsqrtf((float)max(g_deg_s[r], 1));
            float4 o;
            o.x = (acc[i].x + b.x) * sc;
            o.y = (acc[i].y + b.y) * sc;
            o.z = (acc[i].z + b.z) * sc;
            o.w = (acc[i].w + b.w) * sc;
            g_h[(size_t)r * DV + lane] = o;
        }
    }
}

// ---------------------------------------------------------------------------
// One warp per receiver node: register-accumulated gather (no atomics).
__global__ __launch_bounds__(256)
void agg_kernel(float* __restrict__ out, int N) {
    int wg = (blockIdx.x * blockDim.x + threadIdx.x) >> 5;
    int lane = threadIdx.x & 31;
    if (wg >= N) return;

    int beg = g_row_start[wg];
    int end = g_row_start[wg + 1];

    float4 acc = make_float4(0.f, 0.f, 0.f, 0.f);
    int e = beg;
    // 2-deep software pipeline: two independent row loads in flight
    for (; e + 1 < end; e += 2) {
        int s0 = g_edge_src[e];
        int s1 = g_edge_src[e + 1];
        float4 a = g_h[(size_t)s0 * DV + lane];
        float4 c = g_h[(size_t)s1 * DV + lane];
        acc.x += a.x + c.x;
        acc.y += a.y + c.y;
        acc.z += a.z + c.z;
        acc.w += a.w + c.w;
    }
    if (e < end) {
        int s0 = g_edge_src[e];
        float4 a = g_h[(size_t)s0 * DV + lane];
        acc.x += a.x; acc.y += a.y; acc.z += a.z; acc.w += a.w;
    }

    float sc = rsqrtf((float)max(g_deg_r[wg], 1));
    ((float4*)out)[(size_t)wg * DV + lane] =
        make_float4(acc.x * sc, acc.y * sc, acc.z * sc, acc.w * sc);
}

// ---------------------------------------------------------------------------
extern "C" void kernel_launch(void* const* d_in, const int* in_sizes, int n_in,
                              void* d_out, int out_size) {
    const float* x         = (const float*)d_in[0];
    const int*   senders   = (const int*)d_in[1];
    const int*   receivers = (const int*)d_in[2];
    // n_node may or may not appear as a tensor input; index from the end.
    const float* W    = (const float*)d_in[n_in - 2];
    const float* bias = (const float*)d_in[n_in - 1];

    int N = in_sizes[0] / D;
    int E = in_sizes[1];

    static bool attr_set = false;
    if (!attr_set) {
        cudaFuncSetAttribute(gemm_kernel,
                             cudaFuncAttributeMaxDynamicSharedMemorySize,
                             (D * D + 64 * D) * (int)sizeof(float));
        attr_set = true;
    }

    zero_kernel<<<(N + 255) / 256, 256>>>(N);
    degree_kernel<<<(E + 255) / 256, 256>>>(senders, receivers, E);
    scan_kernel<<<1, 1024>>>(N, E);
    gemm_kernel<<<(N + 63) / 64, 256, (D * D + 64 * D) * sizeof(float)>>>(x, W, bias, N);
    fill_kernel<<<(E + 255) / 256, 256>>>(senders, receivers, E);
    agg_kernel<<<(N * 32 + 255) / 256, 256>>>((float*)d_out, N);
}

// round 5
// speedup vs baseline: 1.5101x; 1.5101x over previous
#include <cuda_runtime.h>
#include <cuda_bf16.h>

// GCN: out = Dr^{-1/2} A Ds^{-1/2} (X W + b)
// Pipeline: zero -> degree -> scan(3 passes) -> [GEMM || fill] fused -> gather
// GEMM is dependency-free (deg scales applied in gather via g_sc_s table).

#define MAX_N 100000
#define MAX_E 1600000
#define D 128
#define DV 32          // D/4
#define XS_STRIDE 132  // padded row stride (floats) for Xs, multiple of 4

// ---- device scratch ----
__device__ float g_h[(size_t)MAX_N * D];       // unscaled hidden, 51.2 MB
__device__ float g_sc_s[MAX_N];                // rsqrt(max(deg_s,1))
__device__ float g_sc_r[MAX_N];
__device__ int   g_deg_s[MAX_N];
__device__ int   g_deg_r[MAX_N];
__device__ int   g_row_start[MAX_N + 1];
__device__ int   g_row_cur[MAX_N];
__device__ int   g_edge_src[MAX_E];
__device__ int   g_bsum[256];
__device__ int   g_bpre[256];

// ---------------------------------------------------------------------------
__global__ void zero_kernel(int N) {
    int i = blockIdx.x * blockDim.x + threadIdx.x;
    if (i < N) { g_deg_s[i] = 0; g_deg_r[i] = 0; }
}

__global__ void degree_kernel(const int* __restrict__ senders,
                              const int* __restrict__ receivers, int E) {
    int e = blockIdx.x * blockDim.x + threadIdx.x;
    if (e < E) {
        atomicAdd(&g_deg_s[senders[e]], 1);
        atomicAdd(&g_deg_r[receivers[e]], 1);
    }
}

// ---- 3-pass scan of g_deg_r -> g_row_start/g_row_cur, plus scale tables ----
__global__ void scan1_kernel(int N) {           // per-1024-chunk sums
    __shared__ int red[1024];
    int t = threadIdx.x;
    int i = blockIdx.x * 1024 + t;
    red[t] = (i < N) ? g_deg_r[i] : 0;
    __syncthreads();
    for (int off = 512; off; off >>= 1) {
        if (t < off) red[t] += red[t + off];
        __syncthreads();
    }
    if (t == 0) g_bsum[blockIdx.x] = red[0];
}

__global__ void scan2_kernel(int nb) {          // scan of chunk sums (nb<=256)
    __shared__ int s[256];
    int t = threadIdx.x;
    int v = (t < nb) ? g_bsum[t] : 0;
    s[t] = v;
    __syncthreads();
    for (int off = 1; off < 256; off <<= 1) {
        int tmp = (t >= off) ? s[t - off] : 0;
        __syncthreads();
        s[t] += tmp;
        __syncthreads();
    }
    g_bpre[t] = s[t] - v;                       // exclusive base per chunk
}

__global__ void scan3_kernel(int N) {           // write CSR starts + scales
    __shared__ int s[1024];
    int t = threadIdx.x;
    int i = blockIdx.x * 1024 + t;
    int dr = (i < N) ? g_deg_r[i] : 0;
    s[t] = dr;
    __syncthreads();
    for (int off = 1; off < 1024; off <<= 1) {
        int tmp = (t >= off) ? s[t - off] : 0;
        __syncthreads();
        s[t] += tmp;
        __syncthreads();
    }
    int incl = s[t];
    int base = g_bpre[blockIdx.x];
    if (i < N) {
        int start = base + incl - dr;
        g_row_start[i] = start;
        g_row_cur[i]   = start;
        g_sc_r[i] = rsqrtf((float)max(dr, 1));
        g_sc_s[i] = rsqrtf((float)max(g_deg_s[i], 1));
        if (i == N - 1) g_row_start[N] = base + incl;
    }
}

// ---------------------------------------------------------------------------
// Fused launch: blocks with b%9==0 run a GEMM tile, the rest run CSR fill.
// GEMM: 64-row tile x 128 cols, 128 threads, 8x8 register tile per thread.
__global__ __launch_bounds__(128)
void fused_kernel(const float* __restrict__ x, const float* __restrict__ W,
                  const float* __restrict__ bias,
                  const int* __restrict__ senders,
                  const int* __restrict__ receivers,
                  int N, int E, int nG) {
    int b = blockIdx.x;
    int t = threadIdx.x;

    if (b % 9 == 0) {
        // ---------------- GEMM role ----------------
        int gb = b / 9;
        if (gb >= nG) return;
        extern __shared__ float sm[];
        float* Ws = sm;                         // 128*128 floats, 64 KB
        float* Xs = sm + D * D;                 // 64*132 floats, ~33.8 KB
        float4* Wsv = (float4*)Ws;

        int rowTile = gb * 64;

        const float4* Wv = (const float4*)W;
        for (int i = t; i < D * DV; i += 128) Wsv[i] = Wv[i];

        const float4* Xv = (const float4*)x;
        for (int i = t; i < 64 * DV; i += 128) {
            int r = i >> 5, c4 = i & 31;
            int gr = rowTile + r;
            float4 v = (gr < N) ? Xv[(size_t)gr * DV + c4]
                                : make_float4(0.f, 0.f, 0.f, 0.f);
            ((float4*)(Xs + r * XS_STRIDE))[c4] = v;
        }
        __syncthreads();

        int tx = t & 15, ty = t >> 4;
        int c0 = tx * 8, r0 = ty * 8;

        float4 accA[8], accB[8];
#pragma unroll
        for (int i = 0; i < 8; i++) {
            accA[i] = make_float4(0.f, 0.f, 0.f, 0.f);
            accB[i] = make_float4(0.f, 0.f, 0.f, 0.f);
        }

#pragma unroll 2
        for (int k0 = 0; k0 < D; k0 += 4) {
            float4 xr[8];
#pragma unroll
            for (int i = 0; i < 8; i++)
                xr[i] = *(const float4*)(Xs + (r0 + i) * XS_STRIDE + k0);
#pragma unroll
            for (int j = 0; j < 4; j++) {
                float4 wa = Wsv[(k0 + j) * DV + tx * 2];
                float4 wb = Wsv[(k0 + j) * DV + tx * 2 + 1];
#pragma unroll
                for (int i = 0; i < 8; i++) {
                    float xv = ((const float*)&xr[i])[j];
                    accA[i].x = fmaf(xv, wa.x, accA[i].x);
                    accA[i].y = fmaf(xv, wa.y, accA[i].y);
                    accA[i].z = fmaf(xv, wa.z, accA[i].z);
                    accA[i].w = fmaf(xv, wa.w, accA[i].w);
                    accB[i].x = fmaf(xv, wb.x, accB[i].x);
                    accB[i].y = fmaf(xv, wb.y, accB[i].y);
                    accB[i].z = fmaf(xv, wb.z, accB[i].z);
                    accB[i].w = fmaf(xv, wb.w, accB[i].w);
                }
            }
        }

        float4 ba = ((const float4*)bias)[tx * 2];
        float4 bb = ((const float4*)bias)[tx * 2 + 1];
#pragma unroll
        for (int i = 0; i < 8; i++) {
            int gr = rowTile + r0 + i;
            if (gr < N) {
                float* hp = g_h + (size_t)gr * D + c0;
                float4 oa = make_float4(accA[i].x + ba.x, accA[i].y + ba.y,
                                        accA[i].z + ba.z, accA[i].w + ba.w);
                float4 ob = make_float4(accB[i].x + bb.x, accB[i].y + bb.y,
                                        accB[i].z + bb.z, accB[i].w + bb.w);
                *(float4*)hp       = oa;
                *(float4*)(hp + 4) = ob;
            }
        }
    } else {
        // ---------------- fill role ----------------
        int fb = b - b / 9 - 1;
        int e = fb * 128 + t;
        if (e < E) {
            int pos = atomicAdd(&g_row_cur[receivers[e]], 1);
            g_edge_src[pos] = senders[e];
        }
    }
}

// ---------------------------------------------------------------------------
// One warp per receiver; per-edge prescale by g_sc_s[src], postscale g_sc_r.
__global__ __launch_bounds__(256)
void agg_kernel(float* __restrict__ out, int N) {
    int wg = (blockIdx.x * blockDim.x + threadIdx.x) >> 5;
    int lane = threadIdx.x & 31;
    if (wg >= N) return;

    int beg = g_row_start[wg];
    int end = g_row_start[wg + 1];

    const float4* h4 = (const float4*)g_h;
    float4 acc = make_float4(0.f, 0.f, 0.f, 0.f);
    int e = beg;
    for (; e + 3 < end; e += 4) {
        int s0 = g_edge_src[e],     s1 = g_edge_src[e + 1];
        int s2 = g_edge_src[e + 2], s3 = g_edge_src[e + 3];
        float c0 = g_sc_s[s0], c1 = g_sc_s[s1];
        float c2 = g_sc_s[s2], c3 = g_sc_s[s3];
        float4 a0 = h4[(size_t)s0 * DV + lane];
        float4 a1 = h4[(size_t)s1 * DV + lane];
        float4 a2 = h4[(size_t)s2 * DV + lane];
        float4 a3 = h4[(size_t)s3 * DV + lane];
        acc.x += a0.x * c0 + a1.x * c1 + a2.x * c2 + a3.x * c3;
        acc.y += a0.y * c0 + a1.y * c1 + a2.y * c2 + a3.y * c3;
        acc.z += a0.z * c0 + a1.z * c1 + a2.z * c2 + a3.z * c3;
        acc.w += a0.w * c0 + a1.w * c1 + a2.w * c2 + a3.w * c3;
    }
    for (; e < end; e++) {
        int s0 = g_edge_src[e];
        float c0 = g_sc_s[s0];
        float4 a0 = h4[(size_t)s0 * DV + lane];
        acc.x += a0.x * c0; acc.y += a0.y * c0;
        acc.z += a0.z * c0; acc.w += a0.w * c0;
    }

    float sc = g_sc_r[wg];
    ((float4*)out)[(size_t)wg * DV + lane] =
        make_float4(acc.x * sc, acc.y * sc, acc.z * sc, acc.w * sc);
}

// ---------------------------------------------------------------------------
extern "C" void kernel_launch(void* const* d_in, const int* in_sizes, int n_in,
                              void* d_out, int out_size) {
    const float* x         = (const float*)d_in[0];
    const int*   senders   = (const int*)d_in[1];
    const int*   receivers = (const int*)d_in[2];
    const float* W    = (const float*)d_in[n_in - 2];
    const float* bias = (const float*)d_in[n_in - 1];

    int N = in_sizes[0] / D;
    int E = in_sizes[1];

    const int SMEM = (D * D + 64 * XS_STRIDE) * (int)sizeof(float);  // 99328

    static bool attr_set = false;
    if (!attr_set) {
        cudaFuncSetAttribute(fused_kernel,
                             cudaFuncAttributeMaxDynamicSharedMemorySize, SMEM);
        attr_set = true;
    }

    int nb = (N + 1023) / 1024;               // scan chunks (<=256)
    int nG = (N + 63) / 64;                   // gemm tiles
    int nTot = nG * 9;                        // 1 gemm : 8 fill roles

    zero_kernel  <<<(N + 255) / 256, 256>>>(N);
    degree_kernel<<<(E + 255) / 256, 256>>>(senders, receivers, E);
    scan1_kernel <<<nb, 1024>>>(N);
    scan2_kernel <<<1, 256>>>(nb);
    scan3_kernel <<<nb, 1024>>>(N);
    fused_kernel <<<nTot, 128, SMEM>>>(x, W, bias, senders, receivers, N, E, nG);
    agg_kernel   <<<(N * 32 + 255) / 256, 256>>>((float*)d_out, N);
}

// round 7
// speedup vs baseline: 1.5277x; 1.0117x over previous
#include <cuda_runtime.h>
#include <cuda_bf16.h>
#include <mma.h>
#include <cstdint>

using namespace nvcuda;

// GCN: out = Dr^{-1/2} A Ds^{-1/2} (X W + b)
// zero -> degree -> scan(3) -> [bf16x3 wmma GEMM + fill] -> gather
// 3-term split GEMM: x=xh+xl, W=Wh+Wl; xh*Wh + xh*Wl + xl*Wh  (rel err ~1e-5)

#define MAX_N 100000
#define MAX_E 1600000
#define D 128
#define DV 32
#define SB 136            // bf16 smem row stride (elements), conflict-free LDSM
#define SC 132            // f32 C smem row stride

// smem byte offsets (total 139264)
#define WH_OFF 0
#define WL_OFF 34816
#define XH_OFF 69632
#define XL_OFF 104448
#define SMEM_BYTES 139264

// ---- device scratch ----
__device__ float g_h[(size_t)MAX_N * D];     // prescaled hidden, 51.2 MB
__device__ float g_sc_s[MAX_N];
__device__ float g_sc_r[MAX_N];
__device__ int   g_deg_s[MAX_N];
__device__ int   g_deg_r[MAX_N];
__device__ int   g_row_start[MAX_N + 1];
__device__ int   g_row_cur[MAX_N];
__device__ int   g_edge_src[MAX_E];
__device__ int   g_bsum[256];
__device__ int   g_bpre[256];

// ---------------------------------------------------------------------------
__global__ void zero_kernel(int N) {
    int i = blockIdx.x * blockDim.x + threadIdx.x;
    if (i < N) { g_deg_s[i] = 0; g_deg_r[i] = 0; }
}

__global__ void degree_kernel(const int* __restrict__ senders,
                              const int* __restrict__ receivers, int E) {
    int e = blockIdx.x * blockDim.x + threadIdx.x;
    if (e < E) {
        atomicAdd(&g_deg_s[senders[e]], 1);
        atomicAdd(&g_deg_r[receivers[e]], 1);
    }
}

__global__ void scan1_kernel(int N) {
    __shared__ int red[1024];
    int t = threadIdx.x;
    int i = blockIdx.x * 1024 + t;
    red[t] = (i < N) ? g_deg_r[i] : 0;
    __syncthreads();
    for (int off = 512; off; off >>= 1) {
        if (t < off) red[t] += red[t + off];
        __syncthreads();
    }
    if (t == 0) g_bsum[blockIdx.x] = red[0];
}

__global__ void scan2_kernel(int nb) {
    __shared__ int s[256];
    int t = threadIdx.x;
    int v = (t < nb) ? g_bsum[t] : 0;
    s[t] = v;
    __syncthreads();
    for (int off = 1; off < 256; off <<= 1) {
        int tmp = (t >= off) ? s[t - off] : 0;
        __syncthreads();
        s[t] += tmp;
        __syncthreads();
    }
    g_bpre[t] = s[t] - v;
}

__global__ void scan3_kernel(int N) {
    __shared__ int s[1024];
    int t = threadIdx.x;
    int i = blockIdx.x * 1024 + t;
    int dr = (i < N) ? g_deg_r[i] : 0;
    s[t] = dr;
    __syncthreads();
    for (int off = 1; off < 1024; off <<= 1) {
        int tmp = (t >= off) ? s[t - off] : 0;
        __syncthreads();
        s[t] += tmp;
        __syncthreads();
    }
    int incl = s[t];
    int base = g_bpre[blockIdx.x];
    if (i < N) {
        int start = base + incl - dr;
        g_row_start[i] = start;
        g_row_cur[i]   = start;
        g_sc_r[i] = rsqrtf((float)max(dr, 1));
        g_sc_s[i] = rsqrtf((float)max(g_deg_s[i], 1));
        if (i == N - 1) g_row_start[N] = base + incl;
    }
}

// ---------------------------------------------------------------------------
__device__ __forceinline__ void split_store(__nv_bfloat16* hi, __nv_bfloat16* lo,
                                            int idx, float v) {
    __nv_bfloat16 h = __float2bfloat16(v);
    float r = v - __bfloat162float(h);
    hi[idx] = h;
    lo[idx] = __float2bfloat16(r);
}

// bf16x3 wmma GEMM (128-row tiles) + appended CSR fill phase.
// h[r,:] = (x[r,:] @ W + b) * sc_s[r]
__global__ __launch_bounds__(256)
void gemmfill_kernel(const float* __restrict__ x, const float* __restrict__ W,
                     const float* __restrict__ bias,
                     const int* __restrict__ senders,
                     const int* __restrict__ receivers,
                     int N, int E) {
    extern __shared__ char sm[];
    __nv_bfloat16* Wh = (__nv_bfloat16*)(sm + WH_OFF);
    __nv_bfloat16* Wl = (__nv_bfloat16*)(sm + WL_OFF);
    __nv_bfloat16* Xh = (__nv_bfloat16*)(sm + XH_OFF);
    __nv_bfloat16* Xl = (__nv_bfloat16*)(sm + XL_OFF);
    float*         Cs = (float*)(sm + XH_OFF);    // reused after mma loop

    int t = threadIdx.x;
    int w = t >> 5;
    int rowTile = blockIdx.x * 128;

    // stage W (hi/lo split), [k][n] row-major, stride SB
    const float4* Wv = (const float4*)W;
    for (int i = t; i < D * DV; i += 256) {
        int row = i >> 5, c = (i & 31) * 4;
        float4 v = Wv[i];
        int b0 = row * SB + c;
        split_store(Wh, Wl, b0 + 0, v.x);
        split_store(Wh, Wl, b0 + 1, v.y);
        split_store(Wh, Wl, b0 + 2, v.z);
        split_store(Wh, Wl, b0 + 3, v.w);
    }

    // stage X tile (hi/lo split), [m][k], stride SB
    const float4* Xv = (const float4*)x;
    for (int i = t; i < 128 * DV; i += 256) {
        int row = i >> 5, c = (i & 31) * 4;
        int gr = rowTile + row;
        float4 v = (gr < N) ? Xv[(size_t)gr * DV + (i & 31)]
                            : make_float4(0.f, 0.f, 0.f, 0.f);
        int b0 = row * SB + c;
        split_store(Xh, Xl, b0 + 0, v.x);
        split_store(Xh, Xl, b0 + 1, v.y);
        split_store(Xh, Xl, b0 + 2, v.z);
        split_store(Xh, Xl, b0 + 3, v.w);
    }
    __syncthreads();

    // each warp: rows [w*16, w*16+16), all 128 cols (8 n-tiles)
    wmma::fragment<wmma::accumulator, 16, 16, 16, float> acc[8];
#pragma unroll
    for (int nt = 0; nt < 8; nt++) wmma::fill_fragment(acc[nt], 0.0f);

#pragma unroll
    for (int ks = 0; ks < 8; ks++) {
        wmma::fragment<wmma::matrix_a, 16, 16, 16, __nv_bfloat16, wmma::row_major> ah, al;
        wmma::load_matrix_sync(ah, Xh + (w * 16) * SB + ks * 16, SB);
        wmma::load_matrix_sync(al, Xl + (w * 16) * SB + ks * 16, SB);
#pragma unroll
        for (int nt = 0; nt < 8; nt++) {
            wmma::fragment<wmma::matrix_b, 16, 16, 16, __nv_bfloat16, wmma::row_major> bh, bl;
            wmma::load_matrix_sync(bh, Wh + (ks * 16) * SB + nt * 16, SB);
            wmma::load_matrix_sync(bl, Wl + (ks * 16) * SB + nt * 16, SB);
            wmma::mma_sync(acc[nt], ah, bh, acc[nt]);
            wmma::mma_sync(acc[nt], ah, bl, acc[nt]);
            wmma::mma_sync(acc[nt], al, bh, acc[nt]);
        }
    }

    __syncthreads();   // all warps done reading Xh/Xl before Cs overwrite
#pragma unroll
    for (int nt = 0; nt < 8; nt++)
        wmma::store_matrix_sync(Cs + (w * 16) * SC + nt * 16, acc[nt], SC,
                                wmma::mem_row_major);
    __syncthreads();

    // epilogue: (C + bias) * sc_s -> g_h ; thread t: row=t/2, half=t&1
    {
        int row = t >> 1, half = t & 1;
        int gr = rowTile + row;
        if (gr < N) {
            float scs = g_sc_s[gr];
            const float4* bv = (const float4*)bias;
            float4* hp = (float4*)(g_h + (size_t)gr * D + half * 64);
            const float* cp = Cs + row * SC + half * 64;
#pragma unroll
            for (int q = 0; q < 16; q++) {
                float4 b = bv[half * 16 + q];
                float4 c = *(const float4*)(cp + q * 4);
                float4 o;
                o.x = (c.x + b.x) * scs;
                o.y = (c.y + b.y) * scs;
                o.z = (c.z + b.z) * scs;
                o.w = (c.w + b.w) * scs;
                hp[q] = o;
            }
        }
    }

    // ---------------- fill phase (grid-strided) ----------------
    int gid = blockIdx.x * 256 + t;
    int stride = gridDim.x * 256;
    int e = gid;
    for (; e + stride < E; e += 2 * stride) {
        int r0 = receivers[e], r1 = receivers[e + stride];
        int s0 = senders[e],   s1 = senders[e + stride];
        int p0 = atomicAdd(&g_row_cur[r0], 1);
        int p1 = atomicAdd(&g_row_cur[r1], 1);
        g_edge_src[p0] = s0;
        g_edge_src[p1] = s1;
    }
    if (e < E) {
        int pos = atomicAdd(&g_row_cur[receivers[e]], 1);
        g_edge_src[pos] = senders[e];
    }
}

// ---------------------------------------------------------------------------
// One warp per receiver; h already prescaled; postscale by sc_r.
__global__ __launch_bounds__(256)
void agg_kernel(float* __restrict__ out, int N) {
    int wg = (blockIdx.x * blockDim.x + threadIdx.x) >> 5;
    int lane = threadIdx.x & 31;
    if (wg >= N) return;

    int beg = g_row_start[wg];
    int end = g_row_start[wg + 1];

    const float4* h4 = (const float4*)g_h;
    float4 acc = make_float4(0.f, 0.f, 0.f, 0.f);
    int e = beg;
    for (; e + 3 < end; e += 4) {
        int s0 = g_edge_src[e],     s1 = g_edge_src[e + 1];
        int s2 = g_edge_src[e + 2], s3 = g_edge_src[e + 3];
        float4 a0 = h4[(size_t)s0 * DV + lane];
        float4 a1 = h4[(size_t)s1 * DV + lane];
        float4 a2 = h4[(size_t)s2 * DV + lane];
        float4 a3 = h4[(size_t)s3 * DV + lane];
        acc.x += (a0.x + a1.x) + (a2.x + a3.x);
        acc.y += (a0.y + a1.y) + (a2.y + a3.y);
        acc.z += (a0.z + a1.z) + (a2.z + a3.z);
        acc.w += (a0.w + a1.w) + (a2.w + a3.w);
    }
    for (; e < end; e++) {
        int s0 = g_edge_src[e];
        float4 a0 = h4[(size_t)s0 * DV + lane];
        acc.x += a0.x; acc.y += a0.y; acc.z += a0.z; acc.w += a0.w;
    }

    float sc = g_sc_r[wg];
    ((float4*)out)[(size_t)wg * DV + lane] =
        make_float4(acc.x * sc, acc.y * sc, acc.z * sc, acc.w * sc);
}

// ---------------------------------------------------------------------------
extern "C" void kernel_launch(void* const* d_in, const int* in_sizes, int n_in,
                              void* d_out, int out_size) {
    const float* x         = (const float*)d_in[0];
    const int*   senders   = (const int*)d_in[1];
    const int*   receivers = (const int*)d_in[2];
    const float* W    = (const float*)d_in[n_in - 2];
    const float* bias = (const float*)d_in[n_in - 1];

    int N = in_sizes[0] / D;
    int E = in_sizes[1];

    static bool attr_set = false;
    if (!attr_set) {
        cudaFuncSetAttribute(gemmfill_kernel,
                             cudaFuncAttributeMaxDynamicSharedMemorySize,
                             SMEM_BYTES);
        attr_set = true;
    }

    int nb = (N + 1023) / 1024;
    int nT = (N + 127) / 128;

    zero_kernel   <<<(N + 255) / 256, 256>>>(N);
    degree_kernel <<<(E + 255) / 256, 256>>>(senders, receivers, E);
    scan1_kernel  <<<nb, 1024>>>(N);
    scan2_kernel  <<<1, 256>>>(nb);
    scan3_kernel  <<<nb, 1024>>>(N);
    gemmfill_kernel<<<nT, 256, SMEM_BYTES>>>(x, W, bias, senders, receivers, N, E);
    agg_kernel    <<<(N * 32 + 255) / 256, 256>>>((float*)d_out, N);
}

// round 8
// speedup vs baseline: 1.5730x; 1.0296x over previous
#include <cuda_runtime.h>
#include <cuda_bf16.h>
#include <mma.h>
#include <cstdint>

using namespace nvcuda;

// GCN: out = Dr^{-1/2} A Ds^{-1/2} (X W + b)
// init(zero+Wsplit) -> degree -> scan(lookback, 1 launch) -> [wmma GEMM + fill] -> gather

#define MAX_N 100000
#define MAX_E 1600000
#define D 128
#define DV 32
#define SB 136            // bf16 smem row stride (elements)
#define SC 132            // f32 C smem row stride

#define WH_OFF 0
#define WL_OFF 34816
#define XH_OFF 69632
#define XL_OFF 104448
#define SMEM_BYTES 139264

// ---- device scratch ----
__device__ float g_h[(size_t)MAX_N * D];     // prescaled hidden, 51.2 MB
__device__ __nv_bfloat16 g_Wh[D * D];        // presplit W hi
__device__ __nv_bfloat16 g_Wl[D * D];        // presplit W lo
__device__ float g_sc_s[MAX_N];
__device__ float g_sc_r[MAX_N];
__device__ int   g_deg_s[MAX_N];
__device__ int   g_deg_r[MAX_N];
__device__ int   g_row_start[MAX_N + 1];
__device__ int   g_row_cur[MAX_N];
__device__ int   g_edge_src[MAX_E];
__device__ unsigned long long g_state[256];  // lookback: (flag<<62)|value

// ---------------------------------------------------------------------------
// zero degrees, reset scan state, split W -> bf16 hi/lo
__global__ void init_kernel(const float* __restrict__ W, int N, int nzero) {
    int t = threadIdx.x;
    int b = blockIdx.x;
    if (b < nzero) {
        int i = b * 256 + t;
        if (i < N) { g_deg_s[i] = 0; g_deg_r[i] = 0; }
        if (b == 0) g_state[t] = 0ull;
    } else {
        int idx = (b - nzero) * 256 + t;          // [0, 16384)
        float v = W[idx];
        __nv_bfloat16 h = __float2bfloat16(v);
        g_Wh[idx] = h;
        g_Wl[idx] = __float2bfloat16(v - __bfloat162float(h));
    }
}

__global__ void degree_kernel(const int* __restrict__ senders,
                              const int* __restrict__ receivers, int E) {
    int i = blockIdx.x * blockDim.x + threadIdx.x;
    int e = i * 4;
    if (e + 3 < E) {
        int4 s = *(const int4*)(senders + e);
        int4 r = *(const int4*)(receivers + e);
        atomicAdd(&g_deg_s[s.x], 1); atomicAdd(&g_deg_s[s.y], 1);
        atomicAdd(&g_deg_s[s.z], 1); atomicAdd(&g_deg_s[s.w], 1);
        atomicAdd(&g_deg_r[r.x], 1); atomicAdd(&g_deg_r[r.y], 1);
        atomicAdd(&g_deg_r[r.z], 1); atomicAdd(&g_deg_r[r.w], 1);
    } else {
        for (; e < E; e++) {
            atomicAdd(&g_deg_s[senders[e]], 1);
            atomicAdd(&g_deg_r[receivers[e]], 1);
        }
    }
}

// ---------------------------------------------------------------------------
// Single-pass decoupled-lookback scan of g_deg_r.
// Also writes g_row_start/g_row_cur and the two scale tables.
__global__ __launch_bounds__(1024)
void scan_kernel(int N) {
    __shared__ int s[1024];
    __shared__ int ex_sh;
    int t = threadIdx.x;
    int b = blockIdx.x;
    int i = b * 1024 + t;
    int dr = (i < N) ? g_deg_r[i] : 0;
    s[t] = dr;
    __syncthreads();
    for (int off = 1; off < 1024; off <<= 1) {
        int tmp = (t >= off) ? s[t - off] : 0;
        __syncthreads();
        s[t] += tmp;
        __syncthreads();
    }
    int incl = s[t];
    int total = s[1023];

    if (t == 0) {
        if (b == 0) {
            atomicExch(&g_state[0], (2ull << 62) | (unsigned long long)total);
            ex_sh = 0;
        } else {
            // publish aggregate
            atomicExch(&g_state[b], (1ull << 62) | (unsigned long long)total);
            // lookback
            long long ex = 0;
            int p = b - 1;
            while (true) {
                unsigned long long st;
                do { st = atomicAdd(&g_state[p], 0ull); } while ((st >> 62) == 0);
                ex += (long long)(st & 0x3FFFFFFFFFFFFFFFull);
                if ((st >> 62) == 2ull) break;
                p--;
            }
            atomicExch(&g_state[b],
                       (2ull << 62) | (unsigned long long)(ex + total));
            ex_sh = (int)ex;
        }
    }
    __syncthreads();
    int base = ex_sh;

    if (i < N) {
        int start = base + incl - dr;
        g_row_start[i] = start;
        g_row_cur[i]   = start;
        g_sc_r[i] = rsqrtf((float)max(dr, 1));
        g_sc_s[i] = rsqrtf((float)max(g_deg_s[i], 1));
        if (i == N - 1) g_row_start[N] = base + incl;
    }
}

// ---------------------------------------------------------------------------
__device__ __forceinline__ void split_store(__nv_bfloat16* hi, __nv_bfloat16* lo,
                                            int idx, float v) {
    __nv_bfloat16 h = __float2bfloat16(v);
    float r = v - __bfloat162float(h);
    hi[idx] = h;
    lo[idx] = __float2bfloat16(r);
}

// bf16x3 wmma GEMM (128-row tiles) + appended CSR fill phase.
// h[r,:] = (x[r,:] @ W + b) * sc_s[r]
__global__ __launch_bounds__(256)
void gemmfill_kernel(const float* __restrict__ x, const float* __restrict__ bias,
                     const int* __restrict__ senders,
                     const int* __restrict__ receivers,
                     int N, int E) {
    extern __shared__ char sm[];
    __nv_bfloat16* Wh = (__nv_bfloat16*)(sm + WH_OFF);
    __nv_bfloat16* Wl = (__nv_bfloat16*)(sm + WL_OFF);
    __nv_bfloat16* Xh = (__nv_bfloat16*)(sm + XH_OFF);
    __nv_bfloat16* Xl = (__nv_bfloat16*)(sm + XL_OFF);
    float*         Cs = (float*)(sm + XH_OFF);    // reused after mma loop

    int t = threadIdx.x;
    int w = t >> 5;
    int rowTile = blockIdx.x * 128;

    // stage presplit W: 16B chunks (8 bf16), [k][n] row-major, stride SB
    {
        const uint4* WhG = (const uint4*)g_Wh;
        const uint4* WlG = (const uint4*)g_Wl;
        for (int i = t; i < D * 16; i += 256) {     // 2048 chunks
            int row = i >> 4, c8 = (i & 15) * 8;
            int o = row * SB + c8;
            *(uint4*)(Wh + o) = WhG[i];
            *(uint4*)(Wl + o) = WlG[i];
        }
    }

    // stage X tile (hi/lo split on the fly), [m][k], stride SB
    const float4* Xv = (const float4*)x;
    for (int i = t; i < 128 * DV; i += 256) {
        int row = i >> 5, c = (i & 31) * 4;
        int gr = rowTile + row;
        float4 v = (gr < N) ? Xv[(size_t)gr * DV + (i & 31)]
                            : make_float4(0.f, 0.f, 0.f, 0.f);
        int b0 = row * SB + c;
        split_store(Xh, Xl, b0 + 0, v.x);
        split_store(Xh, Xl, b0 + 1, v.y);
        split_store(Xh, Xl, b0 + 2, v.z);
        split_store(Xh, Xl, b0 + 3, v.w);
    }
    __syncthreads();

    // each warp: rows [w*16, w*16+16), all 128 cols (8 n-tiles)
    wmma::fragment<wmma::accumulator, 16, 16, 16, float> acc[8];
#pragma unroll
    for (int nt = 0; nt < 8; nt++) wmma::fill_fragment(acc[nt], 0.0f);

#pragma unroll
    for (int ks = 0; ks < 8; ks++) {
        wmma::fragment<wmma::matrix_a, 16, 16, 16, __nv_bfloat16, wmma::row_major> ah, al;
        wmma::load_matrix_sync(ah, Xh + (w * 16) * SB + ks * 16, SB);
        wmma::load_matrix_sync(al, Xl + (w * 16) * SB + ks * 16, SB);
#pragma unroll
        for (int nt = 0; nt < 8; nt++) {
            wmma::fragment<wmma::matrix_b, 16, 16, 16, __nv_bfloat16, wmma::row_major> bh, bl;
            wmma::load_matrix_sync(bh, Wh + (ks * 16) * SB + nt * 16, SB);
            wmma::load_matrix_sync(bl, Wl + (ks * 16) * SB + nt * 16, SB);
            wmma::mma_sync(acc[nt], ah, bh, acc[nt]);
            wmma::mma_sync(acc[nt], ah, bl, acc[nt]);
            wmma::mma_sync(acc[nt], al, bh, acc[nt]);
        }
    }

    __syncthreads();   // all warps done reading Xh/Xl before Cs overwrite
#pragma unroll
    for (int nt = 0; nt < 8; nt++)
        wmma::store_matrix_sync(Cs + (w * 16) * SC + nt * 16, acc[nt], SC,
                                wmma::mem_row_major);
    __syncthreads();

    // epilogue: (C + bias) * sc_s -> g_h ; thread t: row=t/2, half=t&1
    {
        int row = t >> 1, half = t & 1;
        int gr = rowTile + row;
        if (gr < N) {
            float scs = g_sc_s[gr];
            const float4* bv = (const float4*)bias;
            float4* hp = (float4*)(g_h + (size_t)gr * D + half * 64);
            const float* cp = Cs + row * SC + half * 64;
#pragma unroll
            for (int q = 0; q < 16; q++) {
                float4 b = bv[half * 16 + q];
                float4 c = *(const float4*)(cp + q * 4);
                float4 o;
                o.x = (c.x + b.x) * scs;
                o.y = (c.y + b.y) * scs;
                o.z = (c.z + b.z) * scs;
                o.w = (c.w + b.w) * scs;
                hp[q] = o;
            }
        }
    }

    // ---------------- fill phase (grid-strided) ----------------
    int gid = blockIdx.x * 256 + t;
    int stride = gridDim.x * 256;
    int e = gid;
    for (; e + stride < E; e += 2 * stride) {
        int r0 = receivers[e], r1 = receivers[e + stride];
        int s0 = senders[e],   s1 = senders[e + stride];
        int p0 = atomicAdd(&g_row_cur[r0], 1);
        int p1 = atomicAdd(&g_row_cur[r1], 1);
        g_edge_src[p0] = s0;
        g_edge_src[p1] = s1;
    }
    if (e < E) {
        int pos = atomicAdd(&g_row_cur[receivers[e]], 1);
        g_edge_src[pos] = senders[e];
    }
}

// ---------------------------------------------------------------------------
// One warp per receiver; h already prescaled; postscale by sc_r. 8-wide unroll.
__global__ __launch_bounds__(256)
void agg_kernel(float* __restrict__ out, int N) {
    int wg = (blockIdx.x * blockDim.x + threadIdx.x) >> 5;
    int lane = threadIdx.x & 31;
    if (wg >= N) return;

    int beg = g_row_start[wg];
    int end = g_row_start[wg + 1];

    const float4* __restrict__ h4 = (const float4*)g_h;
    float4 acc0 = make_float4(0.f, 0.f, 0.f, 0.f);
    float4 acc1 = make_float4(0.f, 0.f, 0.f, 0.f);
    int e = beg;
    for (; e + 7 < end; e += 8) {
        int s0 = g_edge_src[e],     s1 = g_edge_src[e + 1];
        int s2 = g_edge_src[e + 2], s3 = g_edge_src[e + 3];
        int s4 = g_edge_src[e + 4], s5 = g_edge_src[e + 5];
        int s6 = g_edge_src[e + 6], s7 = g_edge_src[e + 7];
        float4 a0 = h4[(size_t)s0 * DV + lane];
        float4 a1 = h4[(size_t)s1 * DV + lane];
        float4 a2 = h4[(size_t)s2 * DV + lane];
        float4 a3 = h4[(size_t)s3 * DV + lane];
        float4 a4 = h4[(size_t)s4 * DV + lane];
        float4 a5 = h4[(size_t)s5 * DV + lane];
        float4 a6 = h4[(size_t)s6 * DV + lane];
        float4 a7 = h4[(size_t)s7 * DV + lane];
        acc0.x += (a0.x + a1.x) + (a2.x + a3.x);
        acc0.y += (a0.y + a1.y) + (a2.y + a3.y);
        acc0.z += (a0.z + a1.z) + (a2.z + a3.z);
        acc0.w += (a0.w + a1.w) + (a2.w + a3.w);
        acc1.x += (a4.x + a5.x) + (a6.x + a7.x);
        acc1.y += (a4.y + a5.y) + (a6.y + a7.y);
        acc1.z += (a4.z + a5.z) + (a6.z + a7.z);
        acc1.w += (a4.w + a5.w) + (a6.w + a7.w);
    }
    for (; e < end; e++) {
        int s0 = g_edge_src[e];
        float4 a0 = h4[(size_t)s0 * DV + lane];
        acc0.x += a0.x; acc0.y += a0.y; acc0.z += a0.z; acc0.w += a0.w;
    }

    float sc = g_sc_r[wg];
    ((float4*)out)[(size_t)wg * DV + lane] =
        make_float4((acc0.x + acc1.x) * sc, (acc0.y + acc1.y) * sc,
                    (acc0.z + acc1.z) * sc, (acc0.w + acc1.w) * sc);
}

// ---------------------------------------------------------------------------
extern "C" void kernel_launch(void* const* d_in, const int* in_sizes, int n_in,
                              void* d_out, int out_size) {
    const float* x         = (const float*)d_in[0];
    const int*   senders   = (const int*)d_in[1];
    const int*   receivers = (const int*)d_in[2];
    const float* W    = (const float*)d_in[n_in - 2];
    const float* bias = (const float*)d_in[n_in - 1];

    int N = in_sizes[0] / D;
    int E = in_sizes[1];

    static bool attr_set = false;
    if (!attr_set) {
        cudaFuncSetAttribute(gemmfill_kernel,
                             cudaFuncAttributeMaxDynamicSharedMemorySize,
                             SMEM_BYTES);
        attr_set = true;
    }

    int nzero = (N + 255) / 256;
    int nSB   = (N + 1023) / 1024;            // <=256 lookback partitions
    int nT    = (N + 127) / 128;
    int nE4   = (E / 4 + 255) / 256 + 1;      // covers tail

    init_kernel   <<<nzero + (D * D) / 256, 256>>>(W, N, nzero);
    degree_kernel <<<nE4, 256>>>(senders, receivers, E);
    scan_kernel   <<<nSB, 1024>>>(N);
    gemmfill_kernel<<<nT, 256, SMEM_BYTES>>>(x, bias, senders, receivers, N, E);
    agg_kernel    <<<(N * 32 + 255) / 256, 256>>>((float*)d_out, N);
}

// round 9
// speedup vs baseline: 1.7960x; 1.1418x over previous
#include <cuda_runtime.h>
#include <cuda_bf16.h>
#include <mma.h>
#include <cstdint>

using namespace nvcuda;

// GCN: out = Dr^{-1/2} A Ds^{-1/2} (X W + b)
// init(zero+Wsplit) -> degree -> scan(lookback) -> [wmma GEMM(64-row,2CTA/SM) + fill] -> gather

#define MAX_N 100000
#define MAX_E 1600000
#define D 128
#define DV 32
#define SB 136            // bf16 smem row stride (elements)
#define SC 132            // f32 C smem row stride

// smem layout (bytes): Wh 34816 | Wl 34816 | Xh 17408 | Xl 17408  = 104448
#define WH_OFF 0
#define WL_OFF 34816
#define XH_OFF 69632
#define XL_OFF 87040
#define SMEM_BYTES 104448
// C (64 x SC f32 = 33792 B) aliases [XH_OFF, XH_OFF+34816)

// ---- device scratch ----
__device__ float g_h[(size_t)MAX_N * D];     // prescaled hidden, 51.2 MB
__device__ __nv_bfloat16 g_Wh[D * D];        // presplit W hi
__device__ __nv_bfloat16 g_Wl[D * D];        // presplit W lo
__device__ float g_sc_s[MAX_N];
__device__ float g_sc_r[MAX_N];
__device__ int   g_deg_s[MAX_N];
__device__ int   g_deg_r[MAX_N];
__device__ int   g_row_start[MAX_N + 1];
__device__ int   g_row_cur[MAX_N];
__device__ int   g_edge_src[MAX_E];
__device__ unsigned long long g_state[256];  // lookback: (flag<<62)|value

// ---------------------------------------------------------------------------
__global__ void init_kernel(const float* __restrict__ W, int N, int nzero) {
    int t = threadIdx.x;
    int b = blockIdx.x;
    if (b < nzero) {
        int i = b * 256 + t;
        if (i < N) { g_deg_s[i] = 0; g_deg_r[i] = 0; }
        if (b == 0) g_state[t] = 0ull;
    } else {
        int idx = (b - nzero) * 256 + t;          // [0, 16384)
        float v = W[idx];
        __nv_bfloat16 h = __float2bfloat16(v);
        g_Wh[idx] = h;
        g_Wl[idx] = __float2bfloat16(v - __bfloat162float(h));
    }
}

__global__ void degree_kernel(const int* __restrict__ senders,
                              const int* __restrict__ receivers, int E) {
    int i = blockIdx.x * blockDim.x + threadIdx.x;
    int e = i * 4;
    if (e + 3 < E) {
        int4 s = *(const int4*)(senders + e);
        int4 r = *(const int4*)(receivers + e);
        atomicAdd(&g_deg_s[s.x], 1); atomicAdd(&g_deg_s[s.y], 1);
        atomicAdd(&g_deg_s[s.z], 1); atomicAdd(&g_deg_s[s.w], 1);
        atomicAdd(&g_deg_r[r.x], 1); atomicAdd(&g_deg_r[r.y], 1);
        atomicAdd(&g_deg_r[r.z], 1); atomicAdd(&g_deg_r[r.w], 1);
    } else {
        for (; e < E; e++) {
            atomicAdd(&g_deg_s[senders[e]], 1);
            atomicAdd(&g_deg_r[receivers[e]], 1);
        }
    }
}

// ---------------------------------------------------------------------------
__global__ __launch_bounds__(1024)
void scan_kernel(int N) {
    __shared__ int s[1024];
    __shared__ int ex_sh;
    int t = threadIdx.x;
    int b = blockIdx.x;
    int i = b * 1024 + t;
    int dr = (i < N) ? g_deg_r[i] : 0;
    s[t] = dr;
    __syncthreads();
    for (int off = 1; off < 1024; off <<= 1) {
        int tmp = (t >= off) ? s[t - off] : 0;
        __syncthreads();
        s[t] += tmp;
        __syncthreads();
    }
    int incl = s[t];
    int total = s[1023];

    if (t == 0) {
        if (b == 0) {
            atomicExch(&g_state[0], (2ull << 62) | (unsigned long long)total);
            ex_sh = 0;
        } else {
            atomicExch(&g_state[b], (1ull << 62) | (unsigned long long)total);
            long long ex = 0;
            int p = b - 1;
            while (true) {
                unsigned long long st;
                do { st = atomicAdd(&g_state[p], 0ull); } while ((st >> 62) == 0);
                ex += (long long)(st & 0x3FFFFFFFFFFFFFFFull);
                if ((st >> 62) == 2ull) break;
                p--;
            }
            atomicExch(&g_state[b],
                       (2ull << 62) | (unsigned long long)(ex + total));
            ex_sh = (int)ex;
        }
    }
    __syncthreads();
    int base = ex_sh;

    if (i < N) {
        int start = base + incl - dr;
        g_row_start[i] = start;
        g_row_cur[i]   = start;
        g_sc_r[i] = rsqrtf((float)max(dr, 1));
        g_sc_s[i] = rsqrtf((float)max(g_deg_s[i], 1));
        if (i == N - 1) g_row_start[N] = base + incl;
    }
}

// ---------------------------------------------------------------------------
__device__ __forceinline__ void split_store(__nv_bfloat16* hi, __nv_bfloat16* lo,
                                            int idx, float v) {
    __nv_bfloat16 h = __float2bfloat16(v);
    float r = v - __bfloat162float(h);
    hi[idx] = h;
    lo[idx] = __float2bfloat16(r);
}

// bf16x3 wmma GEMM, 64-row tiles, 2 CTAs/SM. h[r,:] = (x[r,:] @ W + b) * sc_s[r]
__global__ __launch_bounds__(256, 2)
void gemmfill_kernel(const float* __restrict__ x, const float* __restrict__ bias,
                     const int* __restrict__ senders,
                     const int* __restrict__ receivers,
                     int N, int E) {
    extern __shared__ char sm[];
    __nv_bfloat16* Wh = (__nv_bfloat16*)(sm + WH_OFF);
    __nv_bfloat16* Wl = (__nv_bfloat16*)(sm + WL_OFF);
    __nv_bfloat16* Xh = (__nv_bfloat16*)(sm + XH_OFF);
    __nv_bfloat16* Xl = (__nv_bfloat16*)(sm + XL_OFF);
    float*         Cs = (float*)(sm + XH_OFF);    // aliases Xh/Xl after mma

    int t = threadIdx.x;
    int w = t >> 5;
    int rowTile = blockIdx.x * 64;

    // stage presplit W: 16B chunks (8 bf16), [k][n] row-major, stride SB
    {
        const uint4* WhG = (const uint4*)g_Wh;
        const uint4* WlG = (const uint4*)g_Wl;
        for (int i = t; i < D * 16; i += 256) {     // 2048 chunks
            int row = i >> 4, c8 = (i & 15) * 8;
            int o = row * SB + c8;
            *(uint4*)(Wh + o) = WhG[i];
            *(uint4*)(Wl + o) = WlG[i];
        }
    }

    // stage X tile [64 x 128] (hi/lo split on the fly), stride SB
    const float4* Xv = (const float4*)x;
    for (int i = t; i < 64 * DV; i += 256) {
        int row = i >> 5, c = (i & 31) * 4;
        int gr = rowTile + row;
        float4 v = (gr < N) ? Xv[(size_t)gr * DV + (i & 31)]
                            : make_float4(0.f, 0.f, 0.f, 0.f);
        int b0 = row * SB + c;
        split_store(Xh, Xl, b0 + 0, v.x);
        split_store(Xh, Xl, b0 + 1, v.y);
        split_store(Xh, Xl, b0 + 2, v.z);
        split_store(Xh, Xl, b0 + 3, v.w);
    }
    __syncthreads();

    // warp layout 4x2: wr = rows [wr*16,+16), wc = cols [wc*64,+64) (4 n-tiles)
    int wr = w >> 1, wc = w & 1;
    wmma::fragment<wmma::accumulator, 16, 16, 16, float> acc[4];
#pragma unroll
    for (int nt = 0; nt < 4; nt++) wmma::fill_fragment(acc[nt], 0.0f);

#pragma unroll
    for (int ks = 0; ks < 8; ks++) {
        wmma::fragment<wmma::matrix_a, 16, 16, 16, __nv_bfloat16, wmma::row_major> ah, al;
        wmma::load_matrix_sync(ah, Xh + (wr * 16) * SB + ks * 16, SB);
        wmma::load_matrix_sync(al, Xl + (wr * 16) * SB + ks * 16, SB);
#pragma unroll
        for (int nt = 0; nt < 4; nt++) {
            int col = wc * 64 + nt * 16;
            wmma::fragment<wmma::matrix_b, 16, 16, 16, __nv_bfloat16, wmma::row_major> bh, bl;
            wmma::load_matrix_sync(bh, Wh + (ks * 16) * SB + col, SB);
            wmma::load_matrix_sync(bl, Wl + (ks * 16) * SB + col, SB);
            wmma::mma_sync(acc[nt], ah, bh, acc[nt]);
            wmma::mma_sync(acc[nt], ah, bl, acc[nt]);
            wmma::mma_sync(acc[nt], al, bh, acc[nt]);
        }
    }

    __syncthreads();   // done reading Xh/Xl before Cs overwrite
#pragma unroll
    for (int nt = 0; nt < 4; nt++)
        wmma::store_matrix_sync(Cs + (wr * 16) * SC + wc * 64 + nt * 16,
                                acc[nt], SC, wmma::mem_row_major);
    __syncthreads();

    // epilogue: (C + bias) * sc_s -> g_h ; thread t: row=t>>2, quarter=t&3
    {
        int row = t >> 2, q4 = t & 3;
        int gr = rowTile + row;
        if (gr < N) {
            float scs = g_sc_s[gr];
            const float4* bv = (const float4*)bias;
            float4* hp = (float4*)(g_h + (size_t)gr * D + q4 * 32);
            const float* cp = Cs + row * SC + q4 * 32;
#pragma unroll
            for (int q = 0; q < 8; q++) {
                float4 b = bv[q4 * 8 + q];
                float4 c = *(const float4*)(cp + q * 4);
                float4 o;
                o.x = (c.x + b.x) * scs;
                o.y = (c.y + b.y) * scs;
                o.z = (c.z + b.z) * scs;
                o.w = (c.w + b.w) * scs;
                hp[q] = o;
            }
        }
    }

    // ---------------- fill phase (grid-strided) ----------------
    int gid = blockIdx.x * 256 + t;
    int stride = gridDim.x * 256;
    int e = gid;
    for (; e + stride < E; e += 2 * stride) {
        int r0 = receivers[e], r1 = receivers[e + stride];
        int s0 = senders[e],   s1 = senders[e + stride];
        int p0 = atomicAdd(&g_row_cur[r0], 1);
        int p1 = atomicAdd(&g_row_cur[r1], 1);
        g_edge_src[p0] = s0;
        g_edge_src[p1] = s1;
    }
    if (e < E) {
        int pos = atomicAdd(&g_row_cur[receivers[e]], 1);
        g_edge_src[pos] = senders[e];
    }
}

// ---------------------------------------------------------------------------
// One warp per receiver; h already prescaled; postscale by sc_r. 8-wide unroll.
__global__ __launch_bounds__(256)
void agg_kernel(float* __restrict__ out, int N) {
    int wg = (blockIdx.x * blockDim.x + threadIdx.x) >> 5;
    int lane = threadIdx.x & 31;
    if (wg >= N) return;

    int beg = g_row_start[wg];
    int end = g_row_start[wg + 1];

    const float4* __restrict__ h4 = (const float4*)g_h;
    float4 acc0 = make_float4(0.f, 0.f, 0.f, 0.f);
    float4 acc1 = make_float4(0.f, 0.f, 0.f, 0.f);
    int e = beg;
    for (; e + 7 < end; e += 8) {
        int s0 = g_edge_src[e],     s1 = g_edge_src[e + 1];
        int s2 = g_edge_src[e + 2], s3 = g_edge_src[e + 3];
        int s4 = g_edge_src[e + 4], s5 = g_edge_src[e + 5];
        int s6 = g_edge_src[e + 6], s7 = g_edge_src[e + 7];
        float4 a0 = h4[(size_t)s0 * DV + lane];
        float4 a1 = h4[(size_t)s1 * DV + lane];
        float4 a2 = h4[(size_t)s2 * DV + lane];
        float4 a3 = h4[(size_t)s3 * DV + lane];
        float4 a4 = h4[(size_t)s4 * DV + lane];
        float4 a5 = h4[(size_t)s5 * DV + lane];
        float4 a6 = h4[(size_t)s6 * DV + lane];
        float4 a7 = h4[(size_t)s7 * DV + lane];
        acc0.x += (a0.x + a1.x) + (a2.x + a3.x);
        acc0.y += (a0.y + a1.y) + (a2.y + a3.y);
        acc0.z += (a0.z + a1.z) + (a2.z + a3.z);
        acc0.w += (a0.w + a1.w) + (a2.w + a3.w);
        acc1.x += (a4.x + a5.x) + (a6.x + a7.x);
        acc1.y += (a4.y + a5.y) + (a6.y + a7.y);
        acc1.z += (a4.z + a5.z) + (a6.z + a7.z);
        acc1.w += (a4.w + a5.w) + (a6.w + a7.w);
    }
    for (; e < end; e++) {
        int s0 = g_edge_src[e];
        float4 a0 = h4[(size_t)s0 * DV + lane];
        acc0.x += a0.x; acc0.y += a0.y; acc0.z += a0.z; acc0.w += a0.w;
    }

    float sc = g_sc_r[wg];
    ((float4*)out)[(size_t)wg * DV + lane] =
        make_float4((acc0.x + acc1.x) * sc, (acc0.y + acc1.y) * sc,
                    (acc0.z + acc1.z) * sc, (acc0.w + acc1.w) * sc);
}

// ---------------------------------------------------------------------------
extern "C" void kernel_launch(void* const* d_in, const int* in_sizes, int n_in,
                              void* d_out, int out_size) {
    const float* x         = (const float*)d_in[0];
    const int*   senders   = (const int*)d_in[1];
    const int*   receivers = (const int*)d_in[2];
    const float* W    = (const float*)d_in[n_in - 2];
    const float* bias = (const float*)d_in[n_in - 1];

    int N = in_sizes[0] / D;
    int E = in_sizes[1];

    static bool attr_set = false;
    if (!attr_set) {
        cudaFuncSetAttribute(gemmfill_kernel,
                             cudaFuncAttributeMaxDynamicSharedMemorySize,
                             SMEM_BYTES);
        attr_set = true;
    }

    int nzero = (N + 255) / 256;
    int nSB   = (N + 1023) / 1024;
    int nT    = (N + 63) / 64;
    int nE4   = (E / 4 + 255) / 256 + 1;

    init_kernel   <<<nzero + (D * D) / 256, 256>>>(W, N, nzero);
    degree_kernel <<<nE4, 256>>>(senders, receivers, E);
    scan_kernel   <<<nSB, 1024>>>(N);
    gemmfill_kernel<<<nT, 256, SMEM_BYTES>>>(x, bias, senders, receivers, N, E);
    agg_kernel    <<<(N * 32 + 255) / 256, 256>>>((float*)d_out, N);
}